// round 3
// baseline (speedup 1.0000x reference)
#include <cuda_runtime.h>
#include <math.h>

// Problem constants (from setup_inputs)
#define BQ 2
#define CC 64
#define LH 96
#define LW 96
#define HH 384
#define WW 384
#define DD 256
#define HW_LR (LH*LW)          // 9216
#define NPIX (BQ*HH*WW)        // 294912
#define CIN 266

// Scratch (device globals; no allocation allowed)
__device__ float g_P[(size_t)BQ*4*HW_LR*DD];   // [b][j][p][o]  ~75.5 MB
__device__ float g_sc[BQ*3*HW_LR];             // shortcut MLP output on LR grid
__device__ float g_b00c[DD];                   // b00 + cell-term (pixel-invariant)

// ---------------------------------------------------------------------------
// prep: fold constant rel_cell columns of w00 into the bias
__global__ void k_prep(const float* __restrict__ b00, const float* __restrict__ w00) {
    int o = threadIdx.x;
    if (o >= DD) return;
    float scale_h = (float)HH / (float)LH;
    float scale_w = (float)WW / (float)LW;
    float cell_h = (2.0f / (float)HH) * fmaxf(scale_h * 0.25f, 1.0f) * (float)LH;
    float cell_w = (2.0f / (float)WW) * fmaxf(scale_w * 0.25f, 1.0f) * (float)LW;
    g_b00c[o] = b00[o] + w00[o*CIN + 264] * cell_h + w00[o*CIN + 265] * cell_w;
}

// ---------------------------------------------------------------------------
// shortcut branch: sc = ws2 @ relu(ws1 @ feat + bs1) + bs2 per LR pixel
__global__ void k_short(const float* __restrict__ feat,
                        const float* __restrict__ ws1, const float* __restrict__ bs1,
                        const float* __restrict__ ws2, const float* __restrict__ bs2) {
    __shared__ float s_w1[64*64];
    __shared__ float s_w2[3*64];
    __shared__ float s_b[64];
    int tid = threadIdx.x;
    for (int i = tid; i < 4096; i += 128) s_w1[i] = ws1[i];
    for (int i = tid; i < 192;  i += 128) s_w2[i] = ws2[i];
    if (tid < 64) s_b[tid] = bs1[tid];
    __syncthreads();

    int p  = blockIdx.x * 128 + tid;        // 0..18431
    int b  = p / HW_LR;
    int pp = p - b * HW_LR;

    float f[64];
#pragma unroll
    for (int c = 0; c < 64; c++) f[c] = feat[(b*64 + c) * HW_LR + pp];

    float s0 = bs2[0], s1 = bs2[1], s2 = bs2[2];
#pragma unroll 4
    for (int co = 0; co < 64; co++) {
        float a = s_b[co];
#pragma unroll
        for (int c = 0; c < 64; c++) a += s_w1[co*64 + c] * f[c];
        a = fmaxf(a, 0.0f);
        s0 += s_w2[      co] * a;
        s1 += s_w2[ 64 + co] * a;
        s2 += s_w2[128 + co] * a;
    }
    g_sc[(b*3 + 0)*HW_LR + pp] = s0;
    g_sc[(b*3 + 1)*HW_LR + pp] = s1;
    g_sc[(b*3 + 2)*HW_LR + pp] = s2;
}

// ---------------------------------------------------------------------------
// precompute P[b][j][p][o] = sum_c W00[o][8 + 64j + c] * feat[b][c][p]
// grid: (144 p-tiles of 64, 4 j, 2 b), block 256
__global__ void k_pre(const float* __restrict__ feat, const float* __restrict__ w00) {
    extern __shared__ float sm[];
    float* fs  = sm;              // [64 c][64 px]
    float* wsb = sm + 64*64;      // [64 c][256 o]
    int tid = threadIdx.x;
    int p0 = blockIdx.x * 64;
    int j  = blockIdx.y;
    int b  = blockIdx.z;

    for (int e = tid; e < 64*64; e += 256) {
        int c = e >> 6, pp = e & 63;
        fs[c*64 + pp] = feat[(b*64 + c) * HW_LR + p0 + pp];
    }
    {
        int o = tid;
        const float* wr = w00 + o*CIN + 8 + j*64;
#pragma unroll
        for (int c = 0; c < 64; c++) wsb[c*256 + o] = wr[c];
    }
    __syncthreads();

    int lane = tid & 31, tp = tid >> 5;
    float acc[8][8];
#pragma unroll
    for (int i = 0; i < 8; i++)
#pragma unroll
        for (int r = 0; r < 8; r++) acc[i][r] = 0.0f;

#pragma unroll 4
    for (int c = 0; c < 64; c++) {
        float4 wlo = *(const float4*)&wsb[c*256 + lane*4];
        float4 whi = *(const float4*)&wsb[c*256 + 128 + lane*4];
#pragma unroll
        for (int i = 0; i < 8; i++) {
            float xv = fs[c*64 + tp*8 + i];
            acc[i][0] += wlo.x * xv; acc[i][1] += wlo.y * xv;
            acc[i][2] += wlo.z * xv; acc[i][3] += wlo.w * xv;
            acc[i][4] += whi.x * xv; acc[i][5] += whi.y * xv;
            acc[i][6] += whi.z * xv; acc[i][7] += whi.w * xv;
        }
    }
#pragma unroll
    for (int i = 0; i < 8; i++) {
        int p = p0 + tp*8 + i;
        float* dst = g_P + ((size_t)(b*4 + j) * HW_LR + p) * DD;
        *(float4*)&dst[lane*4]       = make_float4(acc[i][0], acc[i][1], acc[i][2], acc[i][3]);
        *(float4*)&dst[128 + lane*4] = make_float4(acc[i][4], acc[i][5], acc[i][6], acc[i][7]);
    }
}

// ---------------------------------------------------------------------------
// per-HR-pixel geometry (matches JAX reference incl. round-half-to-even)
__device__ __forceinline__ void pixel_geom(int y, int x, float rel[8], float aw[4], int pj[4]) {
    const float invH = 1.0f / (float)HH, invW = 1.0f / (float)WW;
    float cy = -1.0f + invH + (2.0f * invH) * (float)y;
    float cx = -1.0f + invW + (2.0f * invW) * (float)x;
    const float rx = 1.0f / (float)LH;   // shift along height
    const float ry = 1.0f / (float)LW;   // shift along width
    float area[4];
    int jj = 0;
#pragma unroll
    for (int a = 0; a < 2; a++) {
        float vx = a ? 1.0f : -1.0f;
#pragma unroll
        for (int bb = 0; bb < 2; bb++) {
            float vy = bb ? 1.0f : -1.0f;
            float sy = cy + vx * rx + 1e-6f;
            sy = fminf(fmaxf(sy, -1.0f + 1e-6f), 1.0f - 1e-6f);
            float sx = cx + vy * ry + 1e-6f;
            sx = fminf(fmaxf(sx, -1.0f + 1e-6f), 1.0f - 1e-6f);
            float uy = ((sy + 1.0f) * (float)LH - 1.0f) * 0.5f;
            float ux = ((sx + 1.0f) * (float)LW - 1.0f) * 0.5f;
            int iy = min(max(__float2int_rn(uy), 0), LH - 1);
            int ix = min(max(__float2int_rn(ux), 0), LW - 1);
            float oy = -1.0f + 1.0f/(float)LH + (2.0f/(float)LH) * (float)iy;
            float ox = -1.0f + 1.0f/(float)LW + (2.0f/(float)LW) * (float)ix;
            float rly = (cy - oy) * (float)LH;
            float rlx = (cx - ox) * (float)LW;
            rel[2*jj]   = rly;
            rel[2*jj+1] = rlx;
            area[jj] = fabsf(rly * rlx) + 1e-9f;
            pj[jj] = iy * LW + ix;
            jj++;
        }
    }
    float tot = area[0] + area[1] + area[2] + area[3];
    float inv = 1.0f / tot;
    aw[0] = area[3] * inv;   // LIIF swap 0<->3, 1<->2
    aw[1] = area[2] * inv;
    aw[2] = area[1] * inv;
    aw[3] = area[0] * inv;
}

__device__ __forceinline__ float gelu_exact(float v) {
    return 0.5f * v * (1.0f + erff(v * 0.70710678118654752f));
}

// ---------------------------------------------------------------------------
// main fused kernel: gather-P -> x ; t = gelu(W1 x + b1) ; out = W2 t + b2 + shortcut
// block = 256 threads, 64 HR pixels per CTA (contiguous along x; 384 = 6*64)
#define XS_STRIDE 260
__global__ __launch_bounds__(256, 2) void k_main(
        const float* __restrict__ w00,
        const float* __restrict__ w1, const float* __restrict__ b1,
        const float* __restrict__ w2, const float* __restrict__ b2,
        float* __restrict__ out) {
    extern __shared__ float sm[];
    float* xs  = sm;                       // [64 px][260]  (x, later t)
    float* wst = sm + 64*XS_STRIDE;        // [16 k][256 o]
    float* w8s = wst + 16*256;             // [8 k][256 o]  (rel columns of w00)

    int tid = threadIdx.x, lane = tid & 31, wid = tid >> 5;
    int pbase = blockIdx.x * 64;

    // stage 0: load w00 rel columns (transposed), b00c into regs
    {
        int o = tid;
#pragma unroll
        for (int k = 0; k < 8; k++) w8s[k*256 + o] = w00[o*CIN + k];
    }
    float4 bclo = *(const float4*)&g_b00c[lane*4];
    float4 bchi = *(const float4*)&g_b00c[128 + lane*4];
    float4 b1lo = *(const float4*)&b1[lane*4];
    float4 b1hi = *(const float4*)&b1[128 + lane*4];
    __syncthreads();

    // stage 1: each warp computes x for its 8 pixels (o = lane*4..+3, 128+lane*4..+3)
    for (int i = 0; i < 8; i++) {
        int pl = wid*8 + i;
        int g  = pbase + pl;
        int b  = g / (HH*WW);
        int r  = g - b*(HH*WW);
        int y  = r / WW;
        int x  = r - y*WW;
        float rel[8], aw[4];
        int pj[4];
        pixel_geom(y, x, rel, aw, pj);

        float a0 = bclo.x, a1 = bclo.y, a2 = bclo.z, a3 = bclo.w;
        float a4 = bchi.x, a5 = bchi.y, a6 = bchi.z, a7 = bchi.w;
#pragma unroll
        for (int j = 0; j < 4; j++) {
            const float* Pp = g_P + ((size_t)(b*4 + j) * HW_LR + pj[j]) * DD;
            float4 lo = __ldg((const float4*)&Pp[lane*4]);
            float4 hi = __ldg((const float4*)&Pp[128 + lane*4]);
            float s = aw[j];
            a0 += s*lo.x; a1 += s*lo.y; a2 += s*lo.z; a3 += s*lo.w;
            a4 += s*hi.x; a5 += s*hi.y; a6 += s*hi.z; a7 += s*hi.w;
        }
#pragma unroll
        for (int k = 0; k < 8; k++) {
            float rv = rel[k];
            float4 wlo = *(const float4*)&w8s[k*256 + lane*4];
            float4 whi = *(const float4*)&w8s[k*256 + 128 + lane*4];
            a0 += wlo.x*rv; a1 += wlo.y*rv; a2 += wlo.z*rv; a3 += wlo.w*rv;
            a4 += whi.x*rv; a5 += whi.y*rv; a6 += whi.z*rv; a7 += whi.w*rv;
        }
        *(float4*)&xs[pl*XS_STRIDE + lane*4]       = make_float4(a0, a1, a2, a3);
        *(float4*)&xs[pl*XS_STRIDE + 128 + lane*4] = make_float4(a4, a5, a6, a7);
    }
    __syncthreads();

    // stage 2: t = gelu(W1 @ x + b1), 64px x 256o GEMM, K=256
    int tp = wid;  // pixel group = warp id (warp-private rows of xs)
    float acc[8][8];
#pragma unroll
    for (int i = 0; i < 8; i++)
#pragma unroll
        for (int rr = 0; rr < 8; rr++) acc[i][rr] = 0.0f;

    for (int kc = 0; kc < 256; kc += 16) {
        const float* wr = w1 + tid*256 + kc;
        float4 q0 = *(const float4*)&wr[0];
        float4 q1 = *(const float4*)&wr[4];
        float4 q2 = *(const float4*)&wr[8];
        float4 q3 = *(const float4*)&wr[12];
        __syncthreads();
        wst[ 0*256 + tid] = q0.x; wst[ 1*256 + tid] = q0.y;
        wst[ 2*256 + tid] = q0.z; wst[ 3*256 + tid] = q0.w;
        wst[ 4*256 + tid] = q1.x; wst[ 5*256 + tid] = q1.y;
        wst[ 6*256 + tid] = q1.z; wst[ 7*256 + tid] = q1.w;
        wst[ 8*256 + tid] = q2.x; wst[ 9*256 + tid] = q2.y;
        wst[10*256 + tid] = q2.z; wst[11*256 + tid] = q2.w;
        wst[12*256 + tid] = q3.x; wst[13*256 + tid] = q3.y;
        wst[14*256 + tid] = q3.z; wst[15*256 + tid] = q3.w;
        __syncthreads();

#pragma unroll
        for (int ki = 0; ki < 16; ki++) {
            float4 wlo = *(const float4*)&wst[ki*256 + lane*4];
            float4 whi = *(const float4*)&wst[ki*256 + 128 + lane*4];
#pragma unroll
            for (int i = 0; i < 8; i++) {
                float xv = xs[(tp*8 + i)*XS_STRIDE + kc + ki];
                acc[i][0] += wlo.x*xv; acc[i][1] += wlo.y*xv;
                acc[i][2] += wlo.z*xv; acc[i][3] += wlo.w*xv;
                acc[i][4] += whi.x*xv; acc[i][5] += whi.y*xv;
                acc[i][6] += whi.z*xv; acc[i][7] += whi.w*xv;
            }
        }
    }
    __syncwarp();   // all lanes of this warp done reading their xs rows
#pragma unroll
    for (int i = 0; i < 8; i++) {
        int px = tp*8 + i;
        float v0 = gelu_exact(acc[i][0] + b1lo.x);
        float v1 = gelu_exact(acc[i][1] + b1lo.y);
        float v2 = gelu_exact(acc[i][2] + b1lo.z);
        float v3 = gelu_exact(acc[i][3] + b1lo.w);
        float v4 = gelu_exact(acc[i][4] + b1hi.x);
        float v5 = gelu_exact(acc[i][5] + b1hi.y);
        float v6 = gelu_exact(acc[i][6] + b1hi.z);
        float v7 = gelu_exact(acc[i][7] + b1hi.w);
        *(float4*)&xs[px*XS_STRIDE + lane*4]       = make_float4(v0, v1, v2, v3);
        *(float4*)&xs[px*XS_STRIDE + 128 + lane*4] = make_float4(v4, v5, v6, v7);
    }
    __syncthreads();

    // stage 3: out = W2 @ t + b2 + bilinear(shortcut)
    if (tid < 192) {
        int idx = tid;
        int px = idx / 3;
        int c  = idx - px*3;
        int g  = pbase + px;
        int b  = g / (HH*WW);
        int r  = g - b*(HH*WW);
        int y  = r / WW;
        int x  = r - y*WW;

        const float* wr = w2 + c*256;
        const float* tr = xs + px*XS_STRIDE;
        float dot = b2[c];
#pragma unroll 8
        for (int k = 0; k < 256; k += 4) {
            float4 wv = *(const float4*)&wr[k];
            float4 tv = *(const float4*)&tr[k];
            dot += wv.x*tv.x + wv.y*tv.y + wv.z*tv.z + wv.w*tv.w;
        }

        float cy = -1.0f + 1.0f/(float)HH + (2.0f/(float)HH) * (float)y;
        float cx = -1.0f + 1.0f/(float)WW + (2.0f/(float)WW) * (float)x;
        float uy = ((cy + 1.0f) * (float)LH - 1.0f) * 0.5f;
        float ux = ((cx + 1.0f) * (float)LW - 1.0f) * 0.5f;
        float y0f = floorf(uy), x0f = floorf(ux);
        float wy = uy - y0f, wx = ux - x0f;
        int y0 = min(max((int)y0f, 0), LH-1);
        int y1 = min(max((int)y0f + 1, 0), LH-1);
        int x0 = min(max((int)x0f, 0), LW-1);
        int x1 = min(max((int)x0f + 1, 0), LW-1);
        const float* scb = g_sc + (b*3 + c) * HW_LR;
        float samp = scb[y0*LW + x0] * ((1.0f - wy)*(1.0f - wx))
                   + scb[y0*LW + x1] * ((1.0f - wy)*wx)
                   + scb[y1*LW + x0] * (wy*(1.0f - wx))
                   + scb[y1*LW + x1] * (wy*wx);

        out[((size_t)(b*3 + c) * HH + y) * WW + x] = dot + samp;
    }
}

// ---------------------------------------------------------------------------
extern "C" void kernel_launch(void* const* d_in, const int* in_sizes, int n_in,
                              void* d_out, int out_size) {
    const float* feat = (const float*)d_in[0];
    const float* w00  = (const float*)d_in[1];
    const float* b00  = (const float*)d_in[2];
    const float* w1   = (const float*)d_in[3];
    const float* b1   = (const float*)d_in[4];
    const float* w2   = (const float*)d_in[5];
    const float* b2   = (const float*)d_in[6];
    const float* ws1  = (const float*)d_in[7];
    const float* bs1  = (const float*)d_in[8];
    const float* ws2  = (const float*)d_in[9];
    const float* bs2  = (const float*)d_in[10];
    float* out = (float*)d_out;

    static bool attr_done = false;
    size_t smemB = (size_t)(64*64 + 64*256) * sizeof(float);                 // 80 KB
    size_t smemC = (size_t)(64*XS_STRIDE + 16*256 + 8*256) * sizeof(float);  // ~89 KB
    if (!attr_done) {
        cudaFuncSetAttribute(k_pre,  cudaFuncAttributeMaxDynamicSharedMemorySize, (int)smemB);
        cudaFuncSetAttribute(k_main, cudaFuncAttributeMaxDynamicSharedMemorySize, (int)smemC);
        attr_done = true;
    }

    k_prep<<<1, 256>>>(b00, w00);
    k_short<<<HW_LR*BQ/128, 128>>>(feat, ws1, bs1, ws2, bs2);
    k_pre<<<dim3(HW_LR/64, 4, BQ), 256, smemB>>>(feat, w00);
    k_main<<<NPIX/64, 256, smemC>>>(w00, w1, b1, w2, b2, out);
}

// round 6
// speedup vs baseline: 2.1212x; 2.1212x over previous
#include <cuda_runtime.h>
#include <cuda_bf16.h>
#include <math.h>
#include <stdint.h>

#define BQ 2
#define LH 96
#define LW 96
#define HH 384
#define WW 384
#define DD 256
#define HW_LR (LH*LW)
#define NPIX (BQ*HH*WW)
#define CIN 266

// W1 chunk images: 8 chunks, [n=256][k=40 padded] bf16 -> 20480 B per chunk
#define CHB 20480

__device__ float g_P[(size_t)BQ*4*HW_LR*DD];
__device__ float g_sc[BQ*3*HW_LR];
__device__ float g_b00c[DD];
__device__ __align__(16) unsigned char g_w1hi[8*CHB];
__device__ __align__(16) unsigned char g_w1lo[8*CHB];

// ---------------- PTX helpers (baseline ISA only: sm_80-era) ----------------
__device__ __forceinline__ uint32_t smem_u32(const void* p) {
    uint32_t a;
    asm("{ .reg .u64 t; cvta.to.shared.u64 t, %1; cvt.u32.u64 %0, t; }" : "=r"(a) : "l"(p));
    return a;
}
__device__ __forceinline__ void cpa16(uint32_t s, const void* g) {
    asm volatile("cp.async.cg.shared.global [%0], [%1], 16;" :: "r"(s), "l"(g) : "memory");
}
#define CP_COMMIT() asm volatile("cp.async.commit_group;" ::: "memory")
#define CP_WAIT0()  asm volatile("cp.async.wait_group 0;" ::: "memory")
#define CP_WAIT1()  asm volatile("cp.async.wait_group 1;" ::: "memory")

#define LDSM4(r0,r1,r2,r3,addr) \
    asm volatile("ldmatrix.sync.aligned.m8n8.x4.shared.b16 {%0,%1,%2,%3}, [%4];" \
        : "=r"(r0),"=r"(r1),"=r"(r2),"=r"(r3) : "r"(addr))

#define MMA_BF16(d, a, b0, b1) \
    asm volatile("mma.sync.aligned.m16n8k16.row.col.f32.bf16.bf16.f32 " \
        "{%0,%1,%2,%3}, {%4,%5,%6,%7}, {%8,%9}, {%0,%1,%2,%3};" \
        : "+f"((d)[0]),"+f"((d)[1]),"+f"((d)[2]),"+f"((d)[3]) \
        : "r"((a)[0]),"r"((a)[1]),"r"((a)[2]),"r"((a)[3]), "r"(b0),"r"(b1))

__device__ __forceinline__ uint32_t pk(float a, float b) {
    __nv_bfloat162 t = __floats2bfloat162_rn(a, b);
    return *reinterpret_cast<uint32_t*>(&t);
}
__device__ __forceinline__ float hi_of(float v) {
    return __bfloat162float(__float2bfloat16(v));
}

// ---------------- small prep kernels ----------------
__global__ void k_prep(const float* __restrict__ b00, const float* __restrict__ w00) {
    int o = threadIdx.x;
    if (o >= DD) return;
    float cell_h = (2.0f/(float)HH) * fmaxf(((float)HH/(float)LH)*0.25f, 1.0f) * (float)LH;
    float cell_w = (2.0f/(float)WW) * fmaxf(((float)WW/(float)LW)*0.25f, 1.0f) * (float)LW;
    g_b00c[o] = b00[o] + w00[o*CIN + 264]*cell_h + w00[o*CIN + 265]*cell_w;
}

// build padded hi/lo chunk images of w1: chunk kc holds K cols [32kc, 32kc+32)
__global__ void k_wprep(const float* __restrict__ w1) {
    int r = blockIdx.x;      // n row, 0..255
    int c = threadIdx.x;     // k col, 0..255
    float v = w1[r*256 + c];
    float h = hi_of(v);
    int kc = c >> 5, kk = c & 31;
    uint32_t off = (uint32_t)kc*CHB + (uint32_t)r*80 + (uint32_t)kk*2;
    *(__nv_bfloat16*)(g_w1hi + off) = __float2bfloat16(v);
    *(__nv_bfloat16*)(g_w1lo + off) = __float2bfloat16(v - h);
    if (c < 64) {  // zero the 8-element pad of each chunk row
        int kc2 = c >> 3, kk2 = 32 + (c & 7);
        uint32_t o2 = (uint32_t)kc2*CHB + (uint32_t)r*80 + (uint32_t)kk2*2;
        *(__nv_bfloat16*)(g_w1hi + o2) = __float2bfloat16(0.0f);
        *(__nv_bfloat16*)(g_w1lo + o2) = __float2bfloat16(0.0f);
    }
}

__global__ void k_short(const float* __restrict__ feat,
                        const float* __restrict__ ws1, const float* __restrict__ bs1,
                        const float* __restrict__ ws2, const float* __restrict__ bs2) {
    __shared__ float s_w1[64*64];
    __shared__ float s_w2[3*64];
    __shared__ float s_b[64];
    int tid = threadIdx.x;
    for (int i = tid; i < 4096; i += 128) s_w1[i] = ws1[i];
    for (int i = tid; i < 192;  i += 128) s_w2[i] = ws2[i];
    if (tid < 64) s_b[tid] = bs1[tid];
    __syncthreads();
    int p = blockIdx.x * 128 + tid;
    int b = p / HW_LR, pp = p - b*HW_LR;
    float f[64];
#pragma unroll
    for (int c = 0; c < 64; c++) f[c] = feat[(b*64 + c)*HW_LR + pp];
    float s0 = bs2[0], s1 = bs2[1], s2 = bs2[2];
#pragma unroll 4
    for (int co = 0; co < 64; co++) {
        float a = s_b[co];
#pragma unroll
        for (int c = 0; c < 64; c++) a += s_w1[co*64 + c] * f[c];
        a = fmaxf(a, 0.0f);
        s0 += s_w2[co]*a; s1 += s_w2[64+co]*a; s2 += s_w2[128+co]*a;
    }
    g_sc[(b*3+0)*HW_LR + pp] = s0;
    g_sc[(b*3+1)*HW_LR + pp] = s1;
    g_sc[(b*3+2)*HW_LR + pp] = s2;
}

// P[b][j][p][o] = W00_blockj @ feat  (proven R1 kernel)
__global__ void k_pre(const float* __restrict__ feat, const float* __restrict__ w00) {
    extern __shared__ float smf[];
    float* fs  = smf;
    float* wsb = smf + 64*64;
    int tid = threadIdx.x;
    int p0 = blockIdx.x * 64, j = blockIdx.y, b = blockIdx.z;
    for (int e = tid; e < 64*64; e += 256) {
        int c = e >> 6, pp = e & 63;
        fs[c*64 + pp] = feat[(b*64 + c)*HW_LR + p0 + pp];
    }
    {
        const float* wr = w00 + tid*CIN + 8 + j*64;
#pragma unroll
        for (int c = 0; c < 64; c++) wsb[c*256 + tid] = wr[c];
    }
    __syncthreads();
    int lane = tid & 31, tp = tid >> 5;
    float acc[8][8];
#pragma unroll
    for (int i = 0; i < 8; i++)
#pragma unroll
        for (int r = 0; r < 8; r++) acc[i][r] = 0.0f;
#pragma unroll 4
    for (int c = 0; c < 64; c++) {
        float4 wlo = *(const float4*)&wsb[c*256 + lane*4];
        float4 whi = *(const float4*)&wsb[c*256 + 128 + lane*4];
#pragma unroll
        for (int i = 0; i < 8; i++) {
            float xv = fs[c*64 + tp*8 + i];
            acc[i][0] += wlo.x*xv; acc[i][1] += wlo.y*xv; acc[i][2] += wlo.z*xv; acc[i][3] += wlo.w*xv;
            acc[i][4] += whi.x*xv; acc[i][5] += whi.y*xv; acc[i][6] += whi.z*xv; acc[i][7] += whi.w*xv;
        }
    }
#pragma unroll
    for (int i = 0; i < 8; i++) {
        float* dst = g_P + ((size_t)(b*4 + j)*HW_LR + p0 + tp*8 + i)*DD;
        *(float4*)&dst[lane*4]       = make_float4(acc[i][0],acc[i][1],acc[i][2],acc[i][3]);
        *(float4*)&dst[128 + lane*4] = make_float4(acc[i][4],acc[i][5],acc[i][6],acc[i][7]);
    }
}

// ---------------- geometry ----------------
__device__ __forceinline__ void pixel_geom(int y, int x, float rel[8], float aw[4], int pj[4]) {
    float cy = -1.0f + 1.0f/(float)HH + (2.0f/(float)HH)*(float)y;
    float cx = -1.0f + 1.0f/(float)WW + (2.0f/(float)WW)*(float)x;
    const float rx = 1.0f/(float)LH, ry = 1.0f/(float)LW;
    float area[4];
    int jj = 0;
#pragma unroll
    for (int a = 0; a < 2; a++) {
        float vx = a ? 1.0f : -1.0f;
#pragma unroll
        for (int bb = 0; bb < 2; bb++) {
            float vy = bb ? 1.0f : -1.0f;
            float sy = fminf(fmaxf(cy + vx*rx + 1e-6f, -1.0f + 1e-6f), 1.0f - 1e-6f);
            float sx = fminf(fmaxf(cx + vy*ry + 1e-6f, -1.0f + 1e-6f), 1.0f - 1e-6f);
            int iy = min(max(__float2int_rn(((sy + 1.0f)*(float)LH - 1.0f)*0.5f), 0), LH-1);
            int ix = min(max(__float2int_rn(((sx + 1.0f)*(float)LW - 1.0f)*0.5f), 0), LW-1);
            float oy = -1.0f + 1.0f/(float)LH + (2.0f/(float)LH)*(float)iy;
            float ox = -1.0f + 1.0f/(float)LW + (2.0f/(float)LW)*(float)ix;
            float rly = (cy - oy)*(float)LH, rlx = (cx - ox)*(float)LW;
            rel[2*jj] = rly; rel[2*jj+1] = rlx;
            area[jj] = fabsf(rly*rlx) + 1e-9f;
            pj[jj] = iy*LW + ix;
            jj++;
        }
    }
    float inv = 1.0f/(area[0]+area[1]+area[2]+area[3]);
    aw[0] = area[3]*inv; aw[1] = area[2]*inv; aw[2] = area[1]*inv; aw[3] = area[0]*inv;
}
__device__ __forceinline__ float gelu_exact(float v) {
    return 0.5f*v*(1.0f + erff(v*0.70710678118654752f));
}

// ---------------- main fused kernel ----------------
// SMEM map (bytes):
//   xh  [128][264] bf16   @ 0        (67584)
//   xl  [128][264] bf16   @ 67584    (67584)
//   B   2 x (hi 20480 + lo 20480)  @ 135168  (81920)   [w8 overlays buf1 pre-loop]
//   w2  [3][256] f32      @ 217088   (3072)
//   b1  [256] f32         @ 220160   (1024)
//   part[128][3] f32      @ 221184   (1536)
#define OFF_XH   0
#define OFF_XL   67584
#define OFF_B    135168
#define OFF_W2   217088
#define OFF_B1   220160
#define OFF_PART 221184
#define SMEM_MAIN 222720
#define XSTR 264    // bf16 elems per row (528 B)

__global__ __launch_bounds__(512, 1) void k_main(
        const float* __restrict__ w00, const float* __restrict__ b1g,
        const float* __restrict__ w2g, const float* __restrict__ b2g,
        float* __restrict__ out) {
    extern __shared__ char smc[];
    float* s_w2   = (float*)(smc + OFF_W2);
    float* s_b1   = (float*)(smc + OFF_B1);
    float* s_part = (float*)(smc + OFF_PART);
    float* s_w8   = (float*)(smc + OFF_B + 40960);   // overlay on buf1 (8KB)
    uint32_t sbase = smem_u32(smc);

    int tid = threadIdx.x, lane = tid & 31, wid = tid >> 5;
    int pbase = blockIdx.x * 128;
    int b  = pbase / (HH*WW);
    int rr = pbase - b*(HH*WW);
    int y  = rr / WW;
    int x0 = rr - y*WW;

    // stage 0: prefetch W1 chunk 0; load small weights
    {
        const char* hs = (const char*)g_w1hi;
        const char* ls = (const char*)g_w1lo;
        for (int i = tid; i < 1280; i += 512) {
            cpa16(sbase + OFF_B + i*16,         hs + i*16);
            cpa16(sbase + OFF_B + 20480 + i*16, ls + i*16);
        }
        CP_COMMIT();
        for (int o = tid; o < 256; o += 512) {
#pragma unroll
            for (int k = 0; k < 8; k++) s_w8[k*256 + o] = w00[o*CIN + k];
            s_b1[o] = b1g[o];
        }
        for (int i = tid; i < 768; i += 512) s_w2[i] = w2g[i];
    }
    float4 bclo, bchi;
    bclo = *(const float4*)&g_b00c[lane*4];
    bchi = *(const float4*)&g_b00c[128 + lane*4];
    __syncthreads();

    // stage 1: gather x per pixel (fp32), split to bf16 hi/lo in SMEM
    for (int i = 0; i < 8; i++) {
        int pl = wid*8 + i;
        float rel[8], aw[4]; int pj[4];
        pixel_geom(y, x0 + pl, rel, aw, pj);
        float a0=bclo.x,a1=bclo.y,a2=bclo.z,a3=bclo.w;
        float a4=bchi.x,a5=bchi.y,a6=bchi.z,a7=bchi.w;
#pragma unroll
        for (int j = 0; j < 4; j++) {
            const float* Pp = g_P + ((size_t)(b*4 + j)*HW_LR + pj[j])*DD;
            float4 lo = __ldg((const float4*)&Pp[lane*4]);
            float4 hi = __ldg((const float4*)&Pp[128 + lane*4]);
            float s = aw[j];
            a0 += s*lo.x; a1 += s*lo.y; a2 += s*lo.z; a3 += s*lo.w;
            a4 += s*hi.x; a5 += s*hi.y; a6 += s*hi.z; a7 += s*hi.w;
        }
#pragma unroll
        for (int k = 0; k < 8; k++) {
            float rv = rel[k];
            float4 wlo = *(const float4*)&s_w8[k*256 + lane*4];
            float4 whi = *(const float4*)&s_w8[k*256 + 128 + lane*4];
            a0 += wlo.x*rv; a1 += wlo.y*rv; a2 += wlo.z*rv; a3 += wlo.w*rv;
            a4 += whi.x*rv; a5 += whi.y*rv; a6 += whi.z*rv; a7 += whi.w*rv;
        }
        // split and store (hi at OFF_XH, lo at OFF_XL), row stride XSTR bf16
        uint2* dh0 = (uint2*)(smc + OFF_XH + pl*XSTR*2 + lane*8);
        uint2* dh1 = (uint2*)(smc + OFF_XH + pl*XSTR*2 + 256 + lane*8);
        uint2* dl0 = (uint2*)(smc + OFF_XL + pl*XSTR*2 + lane*8);
        uint2* dl1 = (uint2*)(smc + OFF_XL + pl*XSTR*2 + 256 + lane*8);
        *dh0 = make_uint2(pk(a0,a1), pk(a2,a3));
        *dh1 = make_uint2(pk(a4,a5), pk(a6,a7));
        *dl0 = make_uint2(pk(a0-hi_of(a0), a1-hi_of(a1)), pk(a2-hi_of(a2), a3-hi_of(a3)));
        *dl1 = make_uint2(pk(a4-hi_of(a4), a5-hi_of(a5)), pk(a6-hi_of(a6), a7-hi_of(a7)));
    }
    __syncthreads();

    // stage 2: layer1 GEMM via mma.sync bf16 hi/lo (3 passes), K streamed 8x32
    int wm = wid >> 2, wn = wid & 3;     // 4x4 warp grid: m32 x n64 per warp
    float acc[2][8][4];
#pragma unroll
    for (int mt = 0; mt < 2; mt++)
#pragma unroll
        for (int nt = 0; nt < 8; nt++)
#pragma unroll
            for (int q = 0; q < 4; q++) acc[mt][nt][q] = 0.0f;

    for (int kc = 0; kc < 8; kc++) {
        if (kc < 7) {
            const char* hs = (const char*)g_w1hi + (kc+1)*CHB;
            const char* ls = (const char*)g_w1lo + (kc+1)*CHB;
            uint32_t dst = sbase + OFF_B + ((kc+1)&1)*40960;
            for (int i = tid; i < 1280; i += 512) {
                cpa16(dst + i*16,         hs + i*16);
                cpa16(dst + 20480 + i*16, ls + i*16);
            }
            CP_COMMIT();
            CP_WAIT1();
        } else {
            CP_WAIT0();
        }
        __syncthreads();
        uint32_t bufB = sbase + OFF_B + (kc&1)*40960;

#pragma unroll
        for (int k16 = 0; k16 < 2; k16++) {
            int kg = kc*32 + k16*16;
            uint32_t ah[2][4], al[2][4];
#pragma unroll
            for (int mt = 0; mt < 2; mt++) {
                int row = wm*32 + mt*16 + (lane&7) + ((lane>>3)&1)*8;
                int kx  = kg + (lane>>4)*8;
                uint32_t adr = sbase + OFF_XH + row*(XSTR*2) + kx*2;
                LDSM4(ah[mt][0],ah[mt][1],ah[mt][2],ah[mt][3], adr);
                LDSM4(al[mt][0],al[mt][1],al[mt][2],al[mt][3], adr + (OFF_XL - OFF_XH));
            }
            // B fragments: ldmatrix.x4 returns
            //   reg0=(n 0-7,k lo) reg1=(n 8-15,k lo) reg2=(n 0-7,k hi) reg3=(n 8-15,k hi)
            // so regs 1 and 2 go to DIFFERENT n-tiles (fixed from R5).
            uint32_t bf[8][2];
            {
                int nrow = wn*64 + (lane&15);
                int ko   = k16*16 + ((lane>>4)&1)*8;
                uint32_t adr = bufB + nrow*80 + ko*2;   // hi image
#pragma unroll
                for (int p = 0; p < 4; p++)
                    LDSM4(bf[2*p][0],bf[2*p+1][0],bf[2*p][1],bf[2*p+1][1], adr + p*(16*80));
            }
#pragma unroll
            for (int mt = 0; mt < 2; mt++)
#pragma unroll
                for (int nt = 0; nt < 8; nt++) {
                    MMA_BF16(acc[mt][nt], ah[mt], bf[nt][0], bf[nt][1]);
                    MMA_BF16(acc[mt][nt], al[mt], bf[nt][0], bf[nt][1]);
                }
            {
                int nrow = wn*64 + (lane&15);
                int ko   = k16*16 + ((lane>>4)&1)*8;
                uint32_t adr = bufB + 20480 + nrow*80 + ko*2;   // lo image
#pragma unroll
                for (int p = 0; p < 4; p++)
                    LDSM4(bf[2*p][0],bf[2*p+1][0],bf[2*p][1],bf[2*p+1][1], adr + p*(16*80));
            }
#pragma unroll
            for (int mt = 0; mt < 2; mt++)
#pragma unroll
                for (int nt = 0; nt < 8; nt++)
                    MMA_BF16(acc[mt][nt], ah[mt], bf[nt][0], bf[nt][1]);
        }
        __syncthreads();
    }

    // stage 3: epilogue — gelu(D+b1), layer2 partial dots, reduce
    if (tid < 384) s_part[tid] = 0.0f;
    __syncthreads();

#pragma unroll
    for (int mt = 0; mt < 2; mt++) {
        float p0[3] = {0,0,0}, p1[3] = {0,0,0};
#pragma unroll
        for (int nt = 0; nt < 8; nt++) {
            int n0 = wn*64 + nt*8 + (lane&3)*2, n1 = n0 + 1;
            float bb0 = s_b1[n0], bb1 = s_b1[n1];
            float g0 = gelu_exact(acc[mt][nt][0] + bb0);
            float g1 = gelu_exact(acc[mt][nt][1] + bb1);
            float g2 = gelu_exact(acc[mt][nt][2] + bb0);
            float g3 = gelu_exact(acc[mt][nt][3] + bb1);
#pragma unroll
            for (int c = 0; c < 3; c++) {
                float w0 = s_w2[c*256 + n0], w1v = s_w2[c*256 + n1];
                p0[c] += w0*g0 + w1v*g1;
                p1[c] += w0*g2 + w1v*g3;
            }
        }
#pragma unroll
        for (int c = 0; c < 3; c++) {
            p0[c] += __shfl_xor_sync(0xFFFFFFFF, p0[c], 1);
            p0[c] += __shfl_xor_sync(0xFFFFFFFF, p0[c], 2);
            p1[c] += __shfl_xor_sync(0xFFFFFFFF, p1[c], 1);
            p1[c] += __shfl_xor_sync(0xFFFFFFFF, p1[c], 2);
        }
        if ((lane & 3) == 0) {
            int row0 = wm*32 + mt*16 + (lane>>2);
#pragma unroll
            for (int c = 0; c < 3; c++) {
                atomicAdd(&s_part[row0*3 + c],     p0[c]);
                atomicAdd(&s_part[(row0+8)*3 + c], p1[c]);
            }
        }
    }
    __syncthreads();

    // stage 4: + b2 + bilinear shortcut, store
    if (tid < 384) {
        int px = tid / 3, c = tid - px*3;
        int xg = x0 + px;
        float dot = s_part[tid] + b2g[c];
        float cy = -1.0f + 1.0f/(float)HH + (2.0f/(float)HH)*(float)y;
        float cx = -1.0f + 1.0f/(float)WW + (2.0f/(float)WW)*(float)xg;
        float uy = ((cy + 1.0f)*(float)LH - 1.0f)*0.5f;
        float ux = ((cx + 1.0f)*(float)LW - 1.0f)*0.5f;
        float y0f = floorf(uy), x0f = floorf(ux);
        float wy = uy - y0f, wx = ux - x0f;
        int yy0 = min(max((int)y0f, 0), LH-1);
        int yy1 = min(max((int)y0f + 1, 0), LH-1);
        int xx0 = min(max((int)x0f, 0), LW-1);
        int xx1 = min(max((int)x0f + 1, 0), LW-1);
        const float* scb = g_sc + (b*3 + c)*HW_LR;
        float samp = scb[yy0*LW + xx0]*((1.0f-wy)*(1.0f-wx))
                   + scb[yy0*LW + xx1]*((1.0f-wy)*wx)
                   + scb[yy1*LW + xx0]*(wy*(1.0f-wx))
                   + scb[yy1*LW + xx1]*(wy*wx);
        out[((size_t)(b*3 + c)*HH + y)*WW + xg] = dot + samp;
    }
}

// ---------------------------------------------------------------------------
extern "C" void kernel_launch(void* const* d_in, const int* in_sizes, int n_in,
                              void* d_out, int out_size) {
    const float* feat = (const float*)d_in[0];
    const float* w00  = (const float*)d_in[1];
    const float* b00  = (const float*)d_in[2];
    const float* w1   = (const float*)d_in[3];
    const float* b1   = (const float*)d_in[4];
    const float* w2   = (const float*)d_in[5];
    const float* b2   = (const float*)d_in[6];
    const float* ws1  = (const float*)d_in[7];
    const float* bs1  = (const float*)d_in[8];
    const float* ws2  = (const float*)d_in[9];
    const float* bs2  = (const float*)d_in[10];
    float* out = (float*)d_out;

    static bool attr_done = false;
    size_t smemB = (size_t)(64*64 + 64*256)*sizeof(float);
    if (!attr_done) {
        cudaFuncSetAttribute(k_pre,  cudaFuncAttributeMaxDynamicSharedMemorySize, (int)smemB);
        cudaFuncSetAttribute(k_main, cudaFuncAttributeMaxDynamicSharedMemorySize, SMEM_MAIN);
        attr_done = true;
    }

    k_prep<<<1, 256>>>(b00, w00);
    k_wprep<<<256, 256>>>(w1);
    k_short<<<HW_LR*BQ/128, 128>>>(feat, ws1, bs1, ws2, bs2);
    k_pre<<<dim3(HW_LR/64, 4, BQ), 256, smemB>>>(feat, w00);
    k_main<<<NPIX/128, 512, SMEM_MAIN>>>(w00, b1, w2, b2, out);
}

// round 8
// speedup vs baseline: 2.2518x; 1.0616x over previous
#include <cuda_runtime.h>
#include <cuda_bf16.h>
#include <math.h>
#include <stdint.h>

#define BQ 2
#define LH 96
#define LW 96
#define HH 384
#define WW 384
#define DD 256
#define HW_LR (LH*LW)
#define NPIX (BQ*HH*WW)
#define CIN 266

// W1 chunk images: 8 chunks, [n=256][k=40 padded] bf16 -> 20480 B per chunk
#define CHB 20480
// W00 block images: 4 blocks, [n=256][k=80 padded(64 data)] bf16 -> 40960 B each
#define C0B 40960

__device__ float g_P[(size_t)BQ*4*HW_LR*DD];
__device__ float g_sc[BQ*3*HW_LR];
__device__ float g_b00c[DD];
__device__ __align__(16) unsigned char g_w1hi[8*CHB];
__device__ __align__(16) unsigned char g_w1lo[8*CHB];
__device__ __align__(16) unsigned char g_w00bhi[4*C0B];
__device__ __align__(16) unsigned char g_w00blo[4*C0B];

// ---------------- PTX helpers (baseline ISA only: sm_80-era) ----------------
__device__ __forceinline__ uint32_t smem_u32(const void* p) {
    uint32_t a;
    asm("{ .reg .u64 t; cvta.to.shared.u64 t, %1; cvt.u32.u64 %0, t; }" : "=r"(a) : "l"(p));
    return a;
}
__device__ __forceinline__ void cpa16(uint32_t s, const void* g) {
    asm volatile("cp.async.cg.shared.global [%0], [%1], 16;" :: "r"(s), "l"(g) : "memory");
}
#define CP_COMMIT() asm volatile("cp.async.commit_group;" ::: "memory")
#define CP_WAIT0()  asm volatile("cp.async.wait_group 0;" ::: "memory")
#define CP_WAIT1()  asm volatile("cp.async.wait_group 1;" ::: "memory")

#define LDSM4(r0,r1,r2,r3,addr) \
    asm volatile("ldmatrix.sync.aligned.m8n8.x4.shared.b16 {%0,%1,%2,%3}, [%4];" \
        : "=r"(r0),"=r"(r1),"=r"(r2),"=r"(r3) : "r"(addr))

#define MMA_BF16(d, a, b0, b1) \
    asm volatile("mma.sync.aligned.m16n8k16.row.col.f32.bf16.bf16.f32 " \
        "{%0,%1,%2,%3}, {%4,%5,%6,%7}, {%8,%9}, {%0,%1,%2,%3};" \
        : "+f"((d)[0]),"+f"((d)[1]),"+f"((d)[2]),"+f"((d)[3]) \
        : "r"((a)[0]),"r"((a)[1]),"r"((a)[2]),"r"((a)[3]), "r"(b0),"r"(b1))

__device__ __forceinline__ uint32_t pk(float a, float b) {
    __nv_bfloat162 t = __floats2bfloat162_rn(a, b);
    return *reinterpret_cast<uint32_t*>(&t);
}
// fast split: hi = bit-truncated bf16 (packed via PRMT), lo = exact fp32 remainder
__device__ __forceinline__ uint32_t pk_hi(float a, float b) {
    return __byte_perm(__float_as_uint(a), __float_as_uint(b), 0x7632);
}
__device__ __forceinline__ float trunc_bf(float v) {
    return __uint_as_float(__float_as_uint(v) & 0xFFFF0000u);
}
__device__ __forceinline__ float hi_of(float v) {
    return __bfloat162float(__float2bfloat16(v));
}

// ---------------- small prep kernels ----------------
__global__ void k_prep(const float* __restrict__ b00, const float* __restrict__ w00) {
    int o = threadIdx.x;
    if (o >= DD) return;
    float cell_h = (2.0f/(float)HH) * fmaxf(((float)HH/(float)LH)*0.25f, 1.0f) * (float)LH;
    float cell_w = (2.0f/(float)WW) * fmaxf(((float)WW/(float)LW)*0.25f, 1.0f) * (float)LW;
    g_b00c[o] = b00[o] + w00[o*CIN + 264]*cell_h + w00[o*CIN + 265]*cell_w;
}

// build padded hi/lo chunk images of w1: chunk kc holds K cols [32kc, 32kc+32)
__global__ void k_wprep(const float* __restrict__ w1) {
    int r = blockIdx.x;      // n row, 0..255
    int c = threadIdx.x;     // k col, 0..255
    float v = w1[r*256 + c];
    float h = hi_of(v);
    int kc = c >> 5, kk = c & 31;
    uint32_t off = (uint32_t)kc*CHB + (uint32_t)r*80 + (uint32_t)kk*2;
    *(__nv_bfloat16*)(g_w1hi + off) = __float2bfloat16(v);
    *(__nv_bfloat16*)(g_w1lo + off) = __float2bfloat16(v - h);
    if (c < 64) {  // zero the 8-element pad of each chunk row
        int kc2 = c >> 3, kk2 = 32 + (c & 7);
        uint32_t o2 = (uint32_t)kc2*CHB + (uint32_t)r*80 + (uint32_t)kk2*2;
        *(__nv_bfloat16*)(g_w1hi + o2) = __float2bfloat16(0.0f);
        *(__nv_bfloat16*)(g_w1lo + o2) = __float2bfloat16(0.0f);
    }
}

// build hi/lo images of the 4 w00 feat-blocks: [256 n][80 k] (64 data + 16 pad)
__global__ void k_wprep0(const float* __restrict__ w00) {
    int r = blockIdx.x;      // n row 0..255
    int c = threadIdx.x;     // 0..255
    int j = c >> 6, cc = c & 63;
    float v = w00[r*CIN + 8 + j*64 + cc];
    float h = hi_of(v);
    uint32_t off = (uint32_t)j*C0B + (uint32_t)r*160 + (uint32_t)cc*2;
    *(__nv_bfloat16*)(g_w00bhi + off) = __float2bfloat16(v);
    *(__nv_bfloat16*)(g_w00blo + off) = __float2bfloat16(v - h);
    if (c < 64) {  // pad cols 64..79 for all 4 blocks
        int j2 = c >> 4, c2 = 64 + (c & 15);
        uint32_t o2 = (uint32_t)j2*C0B + (uint32_t)r*160 + (uint32_t)c2*2;
        *(__nv_bfloat16*)(g_w00bhi + o2) = __float2bfloat16(0.0f);
        *(__nv_bfloat16*)(g_w00blo + o2) = __float2bfloat16(0.0f);
    }
}

__global__ void k_short(const float* __restrict__ feat,
                        const float* __restrict__ ws1, const float* __restrict__ bs1,
                        const float* __restrict__ ws2, const float* __restrict__ bs2) {
    __shared__ float s_w1[64*64];
    __shared__ float s_w2[3*64];
    __shared__ float s_b[64];
    int tid = threadIdx.x;
    for (int i = tid; i < 4096; i += 128) s_w1[i] = ws1[i];
    for (int i = tid; i < 192;  i += 128) s_w2[i] = ws2[i];
    if (tid < 64) s_b[tid] = bs1[tid];
    __syncthreads();
    int p = blockIdx.x * 128 + tid;
    int b = p / HW_LR, pp = p - b*HW_LR;
    float f[64];
#pragma unroll
    for (int c = 0; c < 64; c++) f[c] = feat[(b*64 + c)*HW_LR + pp];
    float s0 = bs2[0], s1 = bs2[1], s2 = bs2[2];
#pragma unroll 4
    for (int co = 0; co < 64; co++) {
        float a = s_b[co];
#pragma unroll
        for (int c = 0; c < 64; c++) a += s_w1[co*64 + c] * f[c];
        a = fmaxf(a, 0.0f);
        s0 += s_w2[co]*a; s1 += s_w2[64+co]*a; s2 += s_w2[128+co]*a;
    }
    g_sc[(b*3+0)*HW_LR + pp] = s0;
    g_sc[(b*3+1)*HW_LR + pp] = s1;
    g_sc[(b*3+2)*HW_LR + pp] = s2;
}

// ---------------- tensor-core k_pre: P[b][j][p][o] = W00_blockj @ feat ----------------
// grid (72, 4 j, 2 b), block 512. M=128 px, N=256 out, K=64, 3-pass hi/lo mma.
// SMEM: ah [128][80]bf16 @0 (20480) | al @20480 | bh [256][80]bf16 @40960 (40960) | bl @81920
#define P_OFF_AL 20480
#define P_OFF_BH 40960
#define P_OFF_BL 81920
#define SMEM_PRE 122880

__global__ __launch_bounds__(512, 1) void k_pre_mma(const float* __restrict__ feat) {
    extern __shared__ char smc[];
    uint32_t sbase = smem_u32(smc);
    int tid = threadIdx.x, lane = tid & 31, wid = tid >> 5;
    int p0 = blockIdx.x * 128, j = blockIdx.y, b = blockIdx.z;

    // load B images (hi+lo) via cp.async
    {
        const char* hs = (const char*)g_w00bhi + (size_t)j*C0B;
        const char* ls = (const char*)g_w00blo + (size_t)j*C0B;
        for (int i = tid; i < 2560; i += 512) {
            cpa16(sbase + P_OFF_BH + i*16, hs + i*16);
            cpa16(sbase + P_OFF_BL + i*16, ls + i*16);
        }
        CP_COMMIT();
    }
    // build A: feat [c][p] -> A [px][c] bf16 hi/lo, row stride 160 B
    for (int idx = tid; idx < 4096; idx += 512) {
        int px = idx & 127, cp = idx >> 7;   // cp = channel pair 0..31
        float a = feat[(b*64 + 2*cp    )*HW_LR + p0 + px];
        float v = feat[(b*64 + 2*cp + 1)*HW_LR + p0 + px];
        *(uint32_t*)(smc + px*160 + cp*4)            = pk_hi(a, v);
        *(uint32_t*)(smc + P_OFF_AL + px*160 + cp*4) = pk(a - trunc_bf(a), v - trunc_bf(v));
    }
    CP_WAIT0();
    __syncthreads();

    int wm = wid >> 2, wn = wid & 3;
    float acc[2][8][4];
#pragma unroll
    for (int mt = 0; mt < 2; mt++)
#pragma unroll
        for (int nt = 0; nt < 8; nt++)
#pragma unroll
            for (int q = 0; q < 4; q++) acc[mt][nt][q] = 0.0f;

#pragma unroll
    for (int k16 = 0; k16 < 4; k16++) {
        int kg = k16*16;
        uint32_t ah[2][4], al[2][4];
#pragma unroll
        for (int mt = 0; mt < 2; mt++) {
            int row = wm*32 + mt*16 + (lane&7) + ((lane>>3)&1)*8;
            int kx  = kg + (lane>>4)*8;
            uint32_t adr = sbase + row*160 + kx*2;
            LDSM4(ah[mt][0],ah[mt][1],ah[mt][2],ah[mt][3], adr);
            LDSM4(al[mt][0],al[mt][1],al[mt][2],al[mt][3], adr + P_OFF_AL);
        }
        uint32_t bf[8][2];
        {
            int nrow = wn*64 + (lane&15);
            int ko   = kg + ((lane>>4)&1)*8;
            uint32_t adr = sbase + P_OFF_BH + nrow*160 + ko*2;
#pragma unroll
            for (int p = 0; p < 4; p++)
                LDSM4(bf[2*p][0],bf[2*p+1][0],bf[2*p][1],bf[2*p+1][1], adr + p*(16*160));
        }
#pragma unroll
        for (int mt = 0; mt < 2; mt++)
#pragma unroll
            for (int nt = 0; nt < 8; nt++) {
                MMA_BF16(acc[mt][nt], ah[mt], bf[nt][0], bf[nt][1]);
                MMA_BF16(acc[mt][nt], al[mt], bf[nt][0], bf[nt][1]);
            }
        {
            int nrow = wn*64 + (lane&15);
            int ko   = kg + ((lane>>4)&1)*8;
            uint32_t adr = sbase + P_OFF_BL + nrow*160 + ko*2;
#pragma unroll
            for (int p = 0; p < 4; p++)
                LDSM4(bf[2*p][0],bf[2*p+1][0],bf[2*p][1],bf[2*p+1][1], adr + p*(16*160));
        }
#pragma unroll
        for (int mt = 0; mt < 2; mt++)
#pragma unroll
            for (int nt = 0; nt < 8; nt++)
                MMA_BF16(acc[mt][nt], ah[mt], bf[nt][0], bf[nt][1]);
    }

    // store P fp32: acc[mt][nt] = D[row0(+8)][c0(+1)]
    float* Pbase = g_P + ((size_t)(b*4 + j)*HW_LR + p0)*DD;
#pragma unroll
    for (int mt = 0; mt < 2; mt++) {
        int r0 = wm*32 + mt*16 + (lane>>2);
#pragma unroll
        for (int nt = 0; nt < 8; nt++) {
            int c0 = wn*64 + nt*8 + (lane&3)*2;
            *(float2*)&Pbase[(size_t)r0*DD + c0]     = make_float2(acc[mt][nt][0], acc[mt][nt][1]);
            *(float2*)&Pbase[(size_t)(r0+8)*DD + c0] = make_float2(acc[mt][nt][2], acc[mt][nt][3]);
        }
    }
}

// ---------------- geometry ----------------
__device__ __forceinline__ void pixel_geom(int y, int x, float rel[8], float aw[4], int pj[4]) {
    float cy = -1.0f + 1.0f/(float)HH + (2.0f/(float)HH)*(float)y;
    float cx = -1.0f + 1.0f/(float)WW + (2.0f/(float)WW)*(float)x;
    const float rx = 1.0f/(float)LH, ry = 1.0f/(float)LW;
    float area[4];
    int jj = 0;
#pragma unroll
    for (int a = 0; a < 2; a++) {
        float vx = a ? 1.0f : -1.0f;
#pragma unroll
        for (int bb = 0; bb < 2; bb++) {
            float vy = bb ? 1.0f : -1.0f;
            float sy = fminf(fmaxf(cy + vx*rx + 1e-6f, -1.0f + 1e-6f), 1.0f - 1e-6f);
            float sx = fminf(fmaxf(cx + vy*ry + 1e-6f, -1.0f + 1e-6f), 1.0f - 1e-6f);
            int iy = min(max(__float2int_rn(((sy + 1.0f)*(float)LH - 1.0f)*0.5f), 0), LH-1);
            int ix = min(max(__float2int_rn(((sx + 1.0f)*(float)LW - 1.0f)*0.5f), 0), LW-1);
            float oy = -1.0f + 1.0f/(float)LH + (2.0f/(float)LH)*(float)iy;
            float ox = -1.0f + 1.0f/(float)LW + (2.0f/(float)LW)*(float)ix;
            float rly = (cy - oy)*(float)LH, rlx = (cx - ox)*(float)LW;
            rel[2*jj] = rly; rel[2*jj+1] = rlx;
            area[jj] = fabsf(rly*rlx) + 1e-9f;
            pj[jj] = iy*LW + ix;
            jj++;
        }
    }
    float inv = 1.0f/(area[0]+area[1]+area[2]+area[3]);
    aw[0] = area[3]*inv; aw[1] = area[2]*inv; aw[2] = area[1]*inv; aw[3] = area[0]*inv;
}
__device__ __forceinline__ float gelu_exact(float v) {
    return 0.5f*v*(1.0f + erff(v*0.70710678118654752f));
}

// ---------------- main fused kernel ----------------
// SMEM map (bytes):
//   xh  [128][264] bf16   @ 0        (67584)
//   xl  [128][264] bf16   @ 67584    (67584)
//   B   2 x (hi 20480 + lo 20480)  @ 135168  (81920)   [w8 overlays buf1 pre-loop]
//   w2  [3][256] f32      @ 217088   (3072)
//   b1  [256] f32         @ 220160   (1024)
//   part[128][3] f32      @ 221184   (1536)
#define OFF_XH   0
#define OFF_XL   67584
#define OFF_B    135168
#define OFF_W2   217088
#define OFF_B1   220160
#define OFF_PART 221184
#define SMEM_MAIN 222720
#define XSTR 264    // bf16 elems per row (528 B)

__global__ __launch_bounds__(512, 1) void k_main(
        const float* __restrict__ w00, const float* __restrict__ b1g,
        const float* __restrict__ w2g, const float* __restrict__ b2g,
        float* __restrict__ out) {
    extern __shared__ char smc[];
    float* s_w2   = (float*)(smc + OFF_W2);
    float* s_b1   = (float*)(smc + OFF_B1);
    float* s_part = (float*)(smc + OFF_PART);
    float* s_w8   = (float*)(smc + OFF_B + 40960);   // overlay on buf1 (8KB)
    uint32_t sbase = smem_u32(smc);

    int tid = threadIdx.x, lane = tid & 31, wid = tid >> 5;
    int pbase = blockIdx.x * 128;
    int b  = pbase / (HH*WW);
    int rr = pbase - b*(HH*WW);
    int y  = rr / WW;
    int x0 = rr - y*WW;

    // stage 0: prefetch W1 chunk 0; load small weights
    {
        const char* hs = (const char*)g_w1hi;
        const char* ls = (const char*)g_w1lo;
        for (int i = tid; i < 1280; i += 512) {
            cpa16(sbase + OFF_B + i*16,         hs + i*16);
            cpa16(sbase + OFF_B + 20480 + i*16, ls + i*16);
        }
        CP_COMMIT();
        for (int o = tid; o < 256; o += 512) {
#pragma unroll
            for (int k = 0; k < 8; k++) s_w8[k*256 + o] = w00[o*CIN + k];
            s_b1[o] = b1g[o];
        }
        for (int i = tid; i < 768; i += 512) s_w2[i] = w2g[i];
    }
    float4 bclo, bchi;
    bclo = *(const float4*)&g_b00c[lane*4];
    bchi = *(const float4*)&g_b00c[128 + lane*4];
    __syncthreads();

    // stage 1: gather x per pixel (fp32), fast-split to bf16 hi/lo in SMEM
    for (int i = 0; i < 8; i++) {
        int pl = wid*8 + i;
        float rel[8], aw[4]; int pj[4];
        pixel_geom(y, x0 + pl, rel, aw, pj);
        float a0=bclo.x,a1=bclo.y,a2=bclo.z,a3=bclo.w;
        float a4=bchi.x,a5=bchi.y,a6=bchi.z,a7=bchi.w;
#pragma unroll
        for (int j = 0; j < 4; j++) {
            const float* Pp = g_P + ((size_t)(b*4 + j)*HW_LR + pj[j])*DD;
            float4 lo = __ldg((const float4*)&Pp[lane*4]);
            float4 hi = __ldg((const float4*)&Pp[128 + lane*4]);
            float s = aw[j];
            a0 += s*lo.x; a1 += s*lo.y; a2 += s*lo.z; a3 += s*lo.w;
            a4 += s*hi.x; a5 += s*hi.y; a6 += s*hi.z; a7 += s*hi.w;
        }
#pragma unroll
        for (int k = 0; k < 8; k++) {
            float rv = rel[k];
            float4 wlo = *(const float4*)&s_w8[k*256 + lane*4];
            float4 whi = *(const float4*)&s_w8[k*256 + 128 + lane*4];
            a0 += wlo.x*rv; a1 += wlo.y*rv; a2 += wlo.z*rv; a3 += wlo.w*rv;
            a4 += whi.x*rv; a5 += whi.y*rv; a6 += whi.z*rv; a7 += whi.w*rv;
        }
        uint2* dh0 = (uint2*)(smc + OFF_XH + pl*XSTR*2 + lane*8);
        uint2* dh1 = (uint2*)(smc + OFF_XH + pl*XSTR*2 + 256 + lane*8);
        uint2* dl0 = (uint2*)(smc + OFF_XL + pl*XSTR*2 + lane*8);
        uint2* dl1 = (uint2*)(smc + OFF_XL + pl*XSTR*2 + 256 + lane*8);
        *dh0 = make_uint2(pk_hi(a0,a1), pk_hi(a2,a3));
        *dh1 = make_uint2(pk_hi(a4,a5), pk_hi(a6,a7));
        *dl0 = make_uint2(pk(a0-trunc_bf(a0), a1-trunc_bf(a1)), pk(a2-trunc_bf(a2), a3-trunc_bf(a3)));
        *dl1 = make_uint2(pk(a4-trunc_bf(a4), a5-trunc_bf(a5)), pk(a6-trunc_bf(a6), a7-trunc_bf(a7)));
    }
    __syncthreads();

    // stage 2: layer1 GEMM via mma.sync bf16 hi/lo (3 passes), K streamed 8x32
    int wm = wid >> 2, wn = wid & 3;     // 4x4 warp grid: m32 x n64 per warp
    float acc[2][8][4];
#pragma unroll
    for (int mt = 0; mt < 2; mt++)
#pragma unroll
        for (int nt = 0; nt < 8; nt++)
#pragma unroll
            for (int q = 0; q < 4; q++) acc[mt][nt][q] = 0.0f;

    for (int kc = 0; kc < 8; kc++) {
        if (kc < 7) {
            const char* hs = (const char*)g_w1hi + (kc+1)*CHB;
            const char* ls = (const char*)g_w1lo + (kc+1)*CHB;
            uint32_t dst = sbase + OFF_B + ((kc+1)&1)*40960;
            for (int i = tid; i < 1280; i += 512) {
                cpa16(dst + i*16,         hs + i*16);
                cpa16(dst + 20480 + i*16, ls + i*16);
            }
            CP_COMMIT();
            CP_WAIT1();
        } else {
            CP_WAIT0();
        }
        __syncthreads();
        uint32_t bufB = sbase + OFF_B + (kc&1)*40960;

#pragma unroll
        for (int k16 = 0; k16 < 2; k16++) {
            int kg = kc*32 + k16*16;
            uint32_t ah[2][4], al[2][4];
#pragma unroll
            for (int mt = 0; mt < 2; mt++) {
                int row = wm*32 + mt*16 + (lane&7) + ((lane>>3)&1)*8;
                int kx  = kg + (lane>>4)*8;
                uint32_t adr = sbase + OFF_XH + row*(XSTR*2) + kx*2;
                LDSM4(ah[mt][0],ah[mt][1],ah[mt][2],ah[mt][3], adr);
                LDSM4(al[mt][0],al[mt][1],al[mt][2],al[mt][3], adr + (OFF_XL - OFF_XH));
            }
            // B fragments: ldmatrix.x4 returns
            //   reg0=(n 0-7,k lo) reg1=(n 8-15,k lo) reg2=(n 0-7,k hi) reg3=(n 8-15,k hi)
            uint32_t bf[8][2];
            {
                int nrow = wn*64 + (lane&15);
                int ko   = k16*16 + ((lane>>4)&1)*8;
                uint32_t adr = bufB + nrow*80 + ko*2;   // hi image
#pragma unroll
                for (int p = 0; p < 4; p++)
                    LDSM4(bf[2*p][0],bf[2*p+1][0],bf[2*p][1],bf[2*p+1][1], adr + p*(16*80));
            }
#pragma unroll
            for (int mt = 0; mt < 2; mt++)
#pragma unroll
                for (int nt = 0; nt < 8; nt++) {
                    MMA_BF16(acc[mt][nt], ah[mt], bf[nt][0], bf[nt][1]);
                    MMA_BF16(acc[mt][nt], al[mt], bf[nt][0], bf[nt][1]);
                }
            {
                int nrow = wn*64 + (lane&15);
                int ko   = k16*16 + ((lane>>4)&1)*8;
                uint32_t adr = bufB + 20480 + nrow*80 + ko*2;   // lo image
#pragma unroll
                for (int p = 0; p < 4; p++)
                    LDSM4(bf[2*p][0],bf[2*p+1][0],bf[2*p][1],bf[2*p+1][1], adr + p*(16*80));
            }
#pragma unroll
            for (int mt = 0; mt < 2; mt++)
#pragma unroll
                for (int nt = 0; nt < 8; nt++)
                    MMA_BF16(acc[mt][nt], ah[mt], bf[nt][0], bf[nt][1]);
        }
        __syncthreads();
    }

    // stage 3: epilogue — gelu(D+b1), layer2 partial dots, reduce
    if (tid < 384) s_part[tid] = 0.0f;
    __syncthreads();

#pragma unroll
    for (int mt = 0; mt < 2; mt++) {
        float p0[3] = {0,0,0}, p1[3] = {0,0,0};
#pragma unroll
        for (int nt = 0; nt < 8; nt++) {
            int n0 = wn*64 + nt*8 + (lane&3)*2, n1 = n0 + 1;
            float bb0 = s_b1[n0], bb1 = s_b1[n1];
            float g0 = gelu_exact(acc[mt][nt][0] + bb0);
            float g1 = gelu_exact(acc[mt][nt][1] + bb1);
            float g2 = gelu_exact(acc[mt][nt][2] + bb0);
            float g3 = gelu_exact(acc[mt][nt][3] + bb1);
#pragma unroll
            for (int c = 0; c < 3; c++) {
                float w0 = s_w2[c*256 + n0], w1v = s_w2[c*256 + n1];
                p0[c] += w0*g0 + w1v*g1;
                p1[c] += w0*g2 + w1v*g3;
            }
        }
#pragma unroll
        for (int c = 0; c < 3; c++) {
            p0[c] += __shfl_xor_sync(0xFFFFFFFF, p0[c], 1);
            p0[c] += __shfl_xor_sync(0xFFFFFFFF, p0[c], 2);
            p1[c] += __shfl_xor_sync(0xFFFFFFFF, p1[c], 1);
            p1[c] += __shfl_xor_sync(0xFFFFFFFF, p1[c], 2);
        }
        if ((lane & 3) == 0) {
            int row0 = wm*32 + mt*16 + (lane>>2);
#pragma unroll
            for (int c = 0; c < 3; c++) {
                atomicAdd(&s_part[row0*3 + c],     p0[c]);
                atomicAdd(&s_part[(row0+8)*3 + c], p1[c]);
            }
        }
    }
    __syncthreads();

    // stage 4: + b2 + bilinear shortcut, store
    if (tid < 384) {
        int px = tid / 3, c = tid - px*3;
        int xg = x0 + px;
        float dot = s_part[tid] + b2g[c];
        float cy = -1.0f + 1.0f/(float)HH + (2.0f/(float)HH)*(float)y;
        float cx = -1.0f + 1.0f/(float)WW + (2.0f/(float)WW)*(float)xg;
        float uy = ((cy + 1.0f)*(float)LH - 1.0f)*0.5f;
        float ux = ((cx + 1.0f)*(float)LW - 1.0f)*0.5f;
        float y0f = floorf(uy), x0f = floorf(ux);
        float wy = uy - y0f, wx = ux - x0f;
        int yy0 = min(max((int)y0f, 0), LH-1);
        int yy1 = min(max((int)y0f + 1, 0), LH-1);
        int xx0 = min(max((int)x0f, 0), LW-1);
        int xx1 = min(max((int)x0f + 1, 0), LW-1);
        const float* scb = g_sc + (b*3 + c)*HW_LR;
        float samp = scb[yy0*LW + xx0]*((1.0f-wy)*(1.0f-wx))
                   + scb[yy0*LW + xx1]*((1.0f-wy)*wx)
                   + scb[yy1*LW + xx0]*(wy*(1.0f-wx))
                   + scb[yy1*LW + xx1]*(wy*wx);
        out[((size_t)(b*3 + c)*HH + y)*WW + xg] = dot + samp;
    }
}

// ---------------------------------------------------------------------------
extern "C" void kernel_launch(void* const* d_in, const int* in_sizes, int n_in,
                              void* d_out, int out_size) {
    const float* feat = (const float*)d_in[0];
    const float* w00  = (const float*)d_in[1];
    const float* b00  = (const float*)d_in[2];
    const float* w1   = (const float*)d_in[3];
    const float* b1   = (const float*)d_in[4];
    const float* w2   = (const float*)d_in[5];
    const float* b2   = (const float*)d_in[6];
    const float* ws1  = (const float*)d_in[7];
    const float* bs1  = (const float*)d_in[8];
    const float* ws2  = (const float*)d_in[9];
    const float* bs2  = (const float*)d_in[10];
    float* out = (float*)d_out;

    static bool attr_done = false;
    if (!attr_done) {
        cudaFuncSetAttribute(k_pre_mma, cudaFuncAttributeMaxDynamicSharedMemorySize, SMEM_PRE);
        cudaFuncSetAttribute(k_main,    cudaFuncAttributeMaxDynamicSharedMemorySize, SMEM_MAIN);
        attr_done = true;
    }

    k_prep<<<1, 256>>>(b00, w00);
    k_wprep<<<256, 256>>>(w1);
    k_wprep0<<<256, 256>>>(w00);
    k_short<<<HW_LR*BQ/128, 128>>>(feat, ws1, bs1, ws2, bs2);
    k_pre_mma<<<dim3(HW_LR/128, 4, BQ), 512, SMEM_PRE>>>(feat);
    k_main<<<NPIX/128, 512, SMEM_MAIN>>>(w00, b1, w2, b2, out);
}